// round 8
// baseline (speedup 1.0000x reference)
#include <cuda_runtime.h>
#include <cstdint>

#define CH    256
#define FF    512
#define NB    2048
#define BATCH 8
#define BN_COUNT 16384.0f
#define NCTAS 128u
#define NTHREADS 1024

#define MT 128
#define NT 256
#define KC 32
#define A_STRIDE 260        // floats per A row (bank map 4r+t: bijective)
#define B_STRIDE 264        // floats per B row (bank map 8t+r: bijective)

#define A_FL       (128 * A_STRIDE)         // 33280 floats
#define B_BUF_FL   (KC * B_STRIDE)          // 8448 floats
#define OFF_A      0
#define OFF_B      A_FL
#define OFF_RED    (A_FL + 2 * B_BUF_FL)    // 50176
#define SMEM_FL    (OFF_RED + 1024)         // 51200
#define SMEM_BYTES (SMEM_FL * 4)            // 204800 B

// Scratch globals (module-load zeroed; never re-zeroed)
__device__ float    g_Weff[CH * CH];
__device__ float    g_part [128 * 128];
__device__ float    g_partq[128 * 128];
__device__ unsigned g_bar;                  // monotonic ticket counter

__device__ __forceinline__ uint32_t smem_u32(const void* p) {
    uint32_t a;
    asm("{ .reg .u64 t; cvta.to.shared.u64 t, %1; cvt.u32.u64 %0, t; }" : "=r"(a) : "l"(p));
    return a;
}
__device__ __forceinline__ void cp_async16(uint32_t dst, const void* src) {
    asm volatile("cp.async.cg.shared.global [%0], [%1], 16;" :: "r"(dst), "l"(src));
}
__device__ __forceinline__ void cp_commit() {
    asm volatile("cp.async.commit_group;");
}
__device__ __forceinline__ void mma_tf32(float* d, const uint32_t* a, const uint32_t* b) {
    asm volatile(
        "mma.sync.aligned.m16n8k8.row.col.f32.tf32.tf32.f32 "
        "{%0,%1,%2,%3}, {%4,%5,%6,%7}, {%8,%9}, {%0,%1,%2,%3};"
        : "+f"(d[0]), "+f"(d[1]), "+f"(d[2]), "+f"(d[3])
        : "r"(a[0]), "r"(a[1]), "r"(a[2]), "r"(a[3]), "r"(b[0]), "r"(b[1]));
}

// Monotonic grid barrier: no reset, generation from ticket value.
__device__ __forceinline__ void grid_barrier(int tid) {
    __syncthreads();
    if (tid == 0) {
        __threadfence();
        unsigned tck = atomicAdd(&g_bar, 1u);
        unsigned target = (tck & ~(NCTAS - 1u)) + NCTAS;
        unsigned v;
        do {
            asm volatile("ld.acquire.gpu.u32 %0, [%1];" : "=r"(v) : "l"(&g_bar));
        } while ((int)(v - target) < 0);
    }
    __syncthreads();
}

// ---------------------------------------------------------------------------
// THE kernel. grid 128 (1/SM), 1024 threads (32 warps, occ 50%).
// Phase 0: W_eff (FF split over warp halves). Barrier. tf32 mma mainloop.
// Epilogue 1: BN partials. Barrier. Reduce. Epilogue 2: normalize + store.
// Warp tile 32x32: 4x8 warp grid covers the 128x256 CTA tile.
// ---------------------------------------------------------------------------
__global__ void __launch_bounds__(NTHREADS, 1)
mega_kernel(const float* __restrict__ x,
            const float* __restrict__ Wv,
            const float* __restrict__ Wout,
            const float* __restrict__ bout,
            const float* __restrict__ gamma,
            const float* __restrict__ beta,
            float* __restrict__ out) {
    extern __shared__ float smf[];
    uint32_t smb = smem_u32(smf);

    int tid  = threadIdx.x;
    int bid  = blockIdx.x;
    int wid  = tid >> 5;           // 0..31
    int lane = tid & 31;
    int r    = lane >> 2;          // 0..7
    int t    = lane & 3;           // 0..3
    int wRow = wid & 3;            // m * 32
    int wCol = wid >> 2;           // n * 32 (0..7)

    int xt    = bid & 7;
    int yt    = (bid >> 3) & 1;
    int zt    = bid >> 4;
    int n0    = xt * NT;
    int mBase = yt * MT;
    const float* xb = x   + (size_t)zt * CH * NB;
    float*       ob = out + (size_t)zt * CH * NB;

    // ---- prefetch first B chunk (independent of W_eff) ----
    #define LOAD_B(buf, k0)                                                    \
    {                                                                          \
        uint32_t bdst = smb + (OFF_B + (buf) * B_BUF_FL) * 4;                  \
        _Pragma("unroll")                                                      \
        for (int it = 0; it < 2; it++) {                                       \
            int e = tid + it * NTHREADS;  /* 0..2047 float4 slots */           \
            int k = e >> 6, n4 = e & 63;                                       \
            cp_async16(bdst + (k * B_STRIDE + n4 * 4) * 4,                     \
                       &xb[(size_t)((k0) + k) * NB + n0 + n4 * 4]);            \
        }                                                                      \
    }
    LOAD_B(0, 0);
    cp_commit();

    // ---- Phase 0: W_eff slice (16 o x 32 c per CTA), FF split over halves ----
    {
        int halfk = wid >> 4;                           // 0,1
        int ow    = wid & 15;
        int o = ((bid >> 3) & 15) * 16 + ow;
        int c = (bid & 7) * 32 + lane;
        const float* wr = Wout + (size_t)o * FF + halfk * 256;
        const float* vc = Wv + (size_t)halfk * 256 * CH + c;
        float a0 = 0.f, a1 = 0.f, a2 = 0.f, a3 = 0.f;
        #pragma unroll 8
        for (int k = 0; k < 256; k += 4) {
            float4 w = *(const float4*)(wr + k);
            a0 = fmaf(w.x, vc[(size_t)(k + 0) * CH], a0);
            a1 = fmaf(w.y, vc[(size_t)(k + 1) * CH], a1);
            a2 = fmaf(w.z, vc[(size_t)(k + 2) * CH], a2);
            a3 = fmaf(w.w, vc[(size_t)(k + 3) * CH], a3);
        }
        smf[OFF_RED + halfk * 512 + ow * 32 + lane] = (a0 + a1) + (a2 + a3);
    }
    __syncthreads();
    if (tid < 512) {
        int ow = tid >> 5, cc = tid & 31;
        int o = ((bid >> 3) & 15) * 16 + ow;
        int c = (bid & 7) * 32 + cc;
        g_Weff[o * CH + c] = smf[OFF_RED + ow * 32 + cc] +
                             smf[OFF_RED + 512 + ow * 32 + cc];
    }
    grid_barrier(tid);              // W_eff globally visible

    // ---- A resident load: W_eff[mBase:+128, 0:256] -> smem ----
    #pragma unroll
    for (int it = 0; it < 8; it++) {
        int e = tid + it * NTHREADS;     // 0..8191 float4 slots
        int m = e >> 6, c4 = e & 63;
        cp_async16(smb + (OFF_A + m * A_STRIDE + c4 * 4) * 4,
                   &g_Weff[(mBase + m) * CH + c4 * 4]);
    }
    cp_commit();

    if (tid < 256) smf[OFF_RED + tid] = 0.f;

    float acc[2][4][4];
    #pragma unroll
    for (int mt = 0; mt < 2; mt++)
        #pragma unroll
        for (int nt = 0; nt < 4; nt++)
            #pragma unroll
            for (int q = 0; q < 4; q++) acc[mt][nt][q] = 0.f;

    const uint32_t* Au = (const uint32_t*)(smf + OFF_A);

    // ---- mainloop: 8 K-chunks, double-buffered B ----
    for (int i = 0; i < 8; i++) {
        int buf = i & 1;
        if (i < 7) {
            LOAD_B((i + 1) & 1, (i + 1) * KC);
            cp_commit();
            asm volatile("cp.async.wait_group 1;");
        } else {
            asm volatile("cp.async.wait_group 0;");
        }
        __syncthreads();

        const uint32_t* Bu = (const uint32_t*)(smf + OFF_B + buf * B_BUF_FL);

        #pragma unroll
        for (int kc = 0; kc < 4; kc++) {
            int k8  = i * KC + kc * 8;   // A k (global)
            int bk8 = kc * 8;            // B k (chunk-local)
            uint32_t afr[2][4];
            #pragma unroll
            for (int mt = 0; mt < 2; mt++) {
                int m = wRow * 32 + mt * 16 + r;
                afr[mt][0] = Au[m * A_STRIDE + k8 + t];
                afr[mt][1] = Au[(m + 8) * A_STRIDE + k8 + t];
                afr[mt][2] = Au[m * A_STRIDE + k8 + t + 4];
                afr[mt][3] = Au[(m + 8) * A_STRIDE + k8 + t + 4];
            }
            #pragma unroll
            for (int nt = 0; nt < 4; nt++) {
                int n = wCol * 32 + nt * 8 + r;
                uint32_t bfr[2];
                bfr[0] = Bu[(bk8 + t) * B_STRIDE + n];
                bfr[1] = Bu[(bk8 + t + 4) * B_STRIDE + n];
                mma_tf32(acc[0][nt], afr[0], bfr);
                mma_tf32(acc[1][nt], afr[1], bfr);
            }
        }
        __syncthreads();
    }

    // ---- epilogue 1: per-CTA channel partial sums ----
    float* s_red = smf + OFF_RED;
    #pragma unroll
    for (int mt = 0; mt < 2; mt++) {
        #pragma unroll
        for (int rv = 0; rv < 2; rv++) {
            int rl = wRow * 32 + mt * 16 + rv * 8 + r;
            int rg = mBase + rl;
            float bo = bout[rg];
            float ps = 0.f, pq = 0.f;
            #pragma unroll
            for (int nt = 0; nt < 4; nt++) {
                int col = n0 + wCol * 32 + nt * 8 + t * 2;
                size_t gi = (size_t)rg * NB + col;
                float2 xv = *(const float2*)&xb[gi];
                float y0 = xv.x + fmaxf(acc[mt][nt][rv * 2 + 0] + bo, 0.f);
                float y1 = xv.y + fmaxf(acc[mt][nt][rv * 2 + 1] + bo, 0.f);
                ps += y0 + y1;
                pq += y0 * y0 + y1 * y1;
            }
            atomicAdd(&s_red[rl], ps);
            atomicAdd(&s_red[128 + rl], pq);
        }
    }
    __syncthreads();
    if (tid < 128)
        g_part [bid * 128 + tid] = s_red[tid];
    else if (tid < 256)
        g_partq[bid * 128 + (tid - 128)] = s_red[tid];

    grid_barrier(tid);              // all partials visible

    // ---- reduce 64 partials (same m-tile: y==yt) ----
    if (tid < 128) {
        float s = 0.f;
        #pragma unroll 8
        for (int j = 0; j < 64; j++) {
            int pid = (j & 7) + 8 * yt + 16 * (j >> 3);
            s += g_part[pid * 128 + tid];
        }
        s_red[tid] = s;
    } else if (tid < 256) {
        int ch = tid - 128;
        float s = 0.f;
        #pragma unroll 8
        for (int j = 0; j < 64; j++) {
            int pid = (j & 7) + 8 * yt + 16 * (j >> 3);
            s += g_partq[pid * 128 + ch];
        }
        s_red[tid] = s;
    }
    __syncthreads();

    // ---- epilogue 2: recompute y, normalize, single store ----
    #pragma unroll
    for (int mt = 0; mt < 2; mt++) {
        #pragma unroll
        for (int rv = 0; rv < 2; rv++) {
            int rl = wRow * 32 + mt * 16 + rv * 8 + r;
            int rg = mBase + rl;
            float bo = bout[rg];
            float m  = s_red[rl]       * (1.0f / BN_COUNT);
            float vv = s_red[128 + rl] * (1.0f / BN_COUNT) - m * m;
            float sc = gamma[rg] * rsqrtf(vv + 1e-5f);
            float bi = beta[rg] - m * sc;
            #pragma unroll
            for (int nt = 0; nt < 4; nt++) {
                int col = n0 + wCol * 32 + nt * 8 + t * 2;
                size_t gi = (size_t)rg * NB + col;
                float2 xv = *(const float2*)&xb[gi];
                float y0 = xv.x + fmaxf(acc[mt][nt][rv * 2 + 0] + bo, 0.f);
                float y1 = xv.y + fmaxf(acc[mt][nt][rv * 2 + 1] + bo, 0.f);
                *(float2*)&ob[gi] = make_float2(y0 * sc + bi, y1 * sc + bi);
            }
        }
    }
}

// ---------------------------------------------------------------------------
extern "C" void kernel_launch(void* const* d_in, const int* in_sizes, int n_in,
                              void* d_out, int out_size) {
    const float* x     = (const float*)d_in[0];
    // d_in[1]=Wk, d_in[2]=Wq unused (softmax row-sums == 1 -> agg == V)
    const float* Wv    = (const float*)d_in[3];
    const float* Wout  = (const float*)d_in[4];
    const float* bout  = (const float*)d_in[5];
    const float* gamma = (const float*)d_in[6];
    const float* beta  = (const float*)d_in[7];
    float* out = (float*)d_out;

    cudaFuncSetAttribute(mega_kernel,
                         cudaFuncAttributeMaxDynamicSharedMemorySize, SMEM_BYTES);

    mega_kernel<<<NCTAS, NTHREADS, SMEM_BYTES>>>(x, Wv, Wout, bout, gamma, beta, out);
}

// round 9
// speedup vs baseline: 1.3425x; 1.3425x over previous
#include <cuda_runtime.h>
#include <cstdint>

#define CH    256
#define FF    512
#define NB    2048
#define BATCH 8
#define BN_COUNT 16384.0f
#define NCTAS 128u
#define NTHREADS 512

#define MT 128
#define NT 256
#define KC 32
#define A_STRIDE 264        // floats per A row; f2 stride 132 (LDS.64 bank 8r+2t: conflict-free)
#define B_STRIDE 264        // floats per B row (bank 8t+r: bijective)

#define A_FL       (128 * A_STRIDE)         // 33792 floats
#define B_BUF_FL   (KC * B_STRIDE)          // 8448 floats
#define OFF_A      0
#define OFF_B      A_FL
#define OFF_RED    (A_FL + 2 * B_BUF_FL)    // 50688
#define SMEM_FL    (OFF_RED + 256)          // 50944
#define SMEM_BYTES (SMEM_FL * 4)            // 203776 B

// Scratch globals (module-load zeroed; never re-zeroed)
__device__ float    g_Weff[CH * CH];        // column-PERMUTED layout (paired K)
__device__ float    g_part [128 * 128];
__device__ float    g_partq[128 * 128];
__device__ unsigned g_bar;                  // monotonic ticket counter

__device__ __forceinline__ uint32_t smem_u32(const void* p) {
    uint32_t a;
    asm("{ .reg .u64 t; cvta.to.shared.u64 t, %1; cvt.u32.u64 %0, t; }" : "=r"(a) : "l"(p));
    return a;
}
__device__ __forceinline__ void cp_async16(uint32_t dst, const void* src) {
    asm volatile("cp.async.cg.shared.global [%0], [%1], 16;" :: "r"(dst), "l"(src));
}
__device__ __forceinline__ void cp_commit() {
    asm volatile("cp.async.commit_group;");
}
__device__ __forceinline__ void mma_tf32(float* d, const uint32_t* a, const uint32_t* b) {
    asm volatile(
        "mma.sync.aligned.m16n8k8.row.col.f32.tf32.tf32.f32 "
        "{%0,%1,%2,%3}, {%4,%5,%6,%7}, {%8,%9}, {%0,%1,%2,%3};"
        : "+f"(d[0]), "+f"(d[1]), "+f"(d[2]), "+f"(d[3])
        : "r"(a[0]), "r"(a[1]), "r"(a[2]), "r"(a[3]), "r"(b[0]), "r"(b[1]));
}

// Monotonic grid barrier: no reset, generation from ticket value.
__device__ __forceinline__ void grid_barrier(int tid) {
    __syncthreads();
    if (tid == 0) {
        __threadfence();
        unsigned tck = atomicAdd(&g_bar, 1u);
        unsigned target = (tck & ~(NCTAS - 1u)) + NCTAS;
        unsigned v;
        do {
            asm volatile("ld.acquire.gpu.u32 %0, [%1];" : "=r"(v) : "l"(&g_bar));
        } while ((int)(v - target) < 0);
    }
    __syncthreads();
}

// Paired-K column permutation: within each 8-block, k -> (k%4)*2 + k/4
__device__ __forceinline__ int permc(int c) {
    return (c & ~7) | ((c & 3) << 1) | ((c >> 2) & 1);
}

// ---------------------------------------------------------------------------
// THE kernel. grid 128 (1/SM), 512 threads (16 warps).
// Phase 0: W_eff slice (permuted cols). Barrier. tf32 mma mainloop (A resident).
// Epi 1: y -> acc + BN partials. Barrier. Reduce. Epi 2: normalize acc, store.
// Warp tile 32x64: 4x2 warp grid covers the 128x256 CTA tile.
// ---------------------------------------------------------------------------
__global__ void __launch_bounds__(NTHREADS, 1)
mega_kernel(const float* __restrict__ x,
            const float* __restrict__ Wv,
            const float* __restrict__ Wout,
            const float* __restrict__ bout,
            const float* __restrict__ gamma,
            const float* __restrict__ beta,
            float* __restrict__ out) {
    extern __shared__ float smf[];
    uint32_t smb = smem_u32(smf);

    int tid  = threadIdx.x;
    int bid  = blockIdx.x;
    int wid  = tid >> 5;           // 0..15
    int lane = tid & 31;
    int r    = lane >> 2;          // 0..7
    int t    = lane & 3;           // 0..3
    int wRow = wid & 3;            // m * 32
    int wCol = wid >> 2;           // n * 64 (0..3)

    int xt    = bid & 7;
    int yt    = (bid >> 3) & 1;
    int zt    = bid >> 4;
    int n0    = xt * NT;
    int mBase = yt * MT;
    const float* xb = x   + (size_t)zt * CH * NB;
    float*       ob = out + (size_t)zt * CH * NB;

    // ---- prefetch first B chunk (independent of W_eff) ----
    #define LOAD_B(buf, k0)                                                    \
    {                                                                          \
        uint32_t bdst = smb + (OFF_B + (buf) * B_BUF_FL) * 4;                  \
        _Pragma("unroll")                                                      \
        for (int it = 0; it < 4; it++) {                                       \
            int e = tid + it * NTHREADS;  /* 0..2047 float4 slots */           \
            int k = e >> 6, n4 = e & 63;                                       \
            cp_async16(bdst + (k * B_STRIDE + n4 * 4) * 4,                     \
                       &xb[(size_t)((k0) + k) * NB + n0 + n4 * 4]);            \
        }                                                                      \
    }
    LOAD_B(0, 0);
    cp_commit();

    // ---- Phase 0: W_eff slice (16 o x 32 c per CTA), full-K dot, unroll 16 ----
    {
        int o = ((bid >> 3) & 15) * 16 + (tid >> 5);
        int c = (bid & 7) * 32 + (tid & 31);
        const float* wr = Wout + (size_t)o * FF;
        const float* vc = Wv + c;
        float a0 = 0.f, a1 = 0.f, a2 = 0.f, a3 = 0.f;
        #pragma unroll 16
        for (int k = 0; k < FF; k += 4) {
            float4 w = *(const float4*)(wr + k);
            a0 = fmaf(w.x, vc[(size_t)(k + 0) * CH], a0);
            a1 = fmaf(w.y, vc[(size_t)(k + 1) * CH], a1);
            a2 = fmaf(w.z, vc[(size_t)(k + 2) * CH], a2);
            a3 = fmaf(w.w, vc[(size_t)(k + 3) * CH], a3);
        }
        g_Weff[o * CH + permc(c)] = (a0 + a1) + (a2 + a3);
    }
    grid_barrier(tid);              // W_eff globally visible

    // ---- A resident load: W_eff[mBase:+128, 0:256] -> smem (permuted cols) ----
    #pragma unroll
    for (int it = 0; it < 16; it++) {
        int e = tid + it * NTHREADS;     // 0..8191 float4 slots
        int m = e >> 6, c4 = e & 63;
        cp_async16(smb + (OFF_A + m * A_STRIDE + c4 * 4) * 4,
                   &g_Weff[(mBase + m) * CH + c4 * 4]);
    }
    cp_commit();

    if (tid < 256) smf[OFF_RED + tid] = 0.f;

    float acc[2][8][4];
    #pragma unroll
    for (int mt = 0; mt < 2; mt++)
        #pragma unroll
        for (int nt = 0; nt < 8; nt++)
            #pragma unroll
            for (int q = 0; q < 4; q++) acc[mt][nt][q] = 0.f;

    const uint2* Au2 = (const uint2*)(smf + OFF_A);

    // ---- mainloop: 8 K-chunks, double-buffered B ----
    for (int i = 0; i < 8; i++) {
        int buf = i & 1;
        if (i < 7) {
            LOAD_B((i + 1) & 1, (i + 1) * KC);
            cp_commit();
            asm volatile("cp.async.wait_group 1;");
        } else {
            asm volatile("cp.async.wait_group 0;");
        }
        __syncthreads();

        const uint32_t* Bu = (const uint32_t*)(smf + OFF_B + buf * B_BUF_FL);

        #pragma unroll
        for (int kc = 0; kc < 4; kc++) {
            int kk2 = i * 16 + kc * 4;   // paired-K f2 offset (k8/2)
            int bk8 = kc * 8;
            uint32_t afr[2][4];
            #pragma unroll
            for (int mt = 0; mt < 2; mt++) {
                int m = wRow * 32 + mt * 16 + r;
                uint2 p0 = Au2[m * 132 + kk2 + t];
                uint2 p1 = Au2[(m + 8) * 132 + kk2 + t];
                afr[mt][0] = p0.x;   // (r,   k+t)
                afr[mt][1] = p1.x;   // (r+8, k+t)
                afr[mt][2] = p0.y;   // (r,   k+t+4)
                afr[mt][3] = p1.y;   // (r+8, k+t+4)
            }
            #pragma unroll
            for (int nt = 0; nt < 8; nt++) {
                int n = wCol * 64 + nt * 8 + r;
                uint32_t bfr[2];
                bfr[0] = Bu[(bk8 + t) * B_STRIDE + n];
                bfr[1] = Bu[(bk8 + t + 4) * B_STRIDE + n];
                mma_tf32(acc[0][nt], afr[0], bfr);
                mma_tf32(acc[1][nt], afr[1], bfr);
            }
        }
        __syncthreads();
    }

    // ---- epilogue 1: fold y into acc, accumulate per-CTA BN partials ----
    float* s_red = smf + OFF_RED;
    #pragma unroll
    for (int mt = 0; mt < 2; mt++) {
        #pragma unroll
        for (int rv = 0; rv < 2; rv++) {
            int rl = wRow * 32 + mt * 16 + rv * 8 + r;
            int rg = mBase + rl;
            float bo = bout[rg];
            float ps = 0.f, pq = 0.f;
            #pragma unroll
            for (int nt = 0; nt < 8; nt++) {
                int col = n0 + wCol * 64 + nt * 8 + t * 2;
                size_t gi = (size_t)rg * NB + col;
                float2 xv = *(const float2*)&xb[gi];
                float y0 = xv.x + fmaxf(acc[mt][nt][rv * 2 + 0] + bo, 0.f);
                float y1 = xv.y + fmaxf(acc[mt][nt][rv * 2 + 1] + bo, 0.f);
                acc[mt][nt][rv * 2 + 0] = y0;   // acc now holds y
                acc[mt][nt][rv * 2 + 1] = y1;
                ps += y0 + y1;
                pq += y0 * y0 + y1 * y1;
            }
            atomicAdd(&s_red[rl], ps);
            atomicAdd(&s_red[128 + rl], pq);
        }
    }
    __syncthreads();
    if (tid < 128)
        g_part [bid * 128 + tid] = s_red[tid];
    else if (tid < 256)
        g_partq[bid * 128 + (tid - 128)] = s_red[tid];

    grid_barrier(tid);              // all partials visible

    // ---- reduce 64 partials (same m-tile: y==yt) ----
    if (tid < 128) {
        float s = 0.f;
        #pragma unroll 8
        for (int j = 0; j < 64; j++) {
            int pid = (j & 7) + 8 * yt + 16 * (j >> 3);
            s += g_part[pid * 128 + tid];
        }
        s_red[tid] = s;
    } else if (tid < 256) {
        int ch = tid - 128;
        float s = 0.f;
        #pragma unroll 8
        for (int j = 0; j < 64; j++) {
            int pid = (j & 7) + 8 * yt + 16 * (j >> 3);
            s += g_partq[pid * 128 + ch];
        }
        s_red[tid] = s;
    }
    __syncthreads();

    // ---- epilogue 2: normalize register-resident y, single store ----
    #pragma unroll
    for (int mt = 0; mt < 2; mt++) {
        #pragma unroll
        for (int rv = 0; rv < 2; rv++) {
            int rl = wRow * 32 + mt * 16 + rv * 8 + r;
            int rg = mBase + rl;
            float m  = s_red[rl]       * (1.0f / BN_COUNT);
            float vv = s_red[128 + rl] * (1.0f / BN_COUNT) - m * m;
            float sc = gamma[rg] * rsqrtf(vv + 1e-5f);
            float bi = beta[rg] - m * sc;
            #pragma unroll
            for (int nt = 0; nt < 8; nt++) {
                int col = n0 + wCol * 64 + nt * 8 + t * 2;
                size_t gi = (size_t)rg * NB + col;
                float y0 = acc[mt][nt][rv * 2 + 0];
                float y1 = acc[mt][nt][rv * 2 + 1];
                *(float2*)&ob[gi] = make_float2(y0 * sc + bi, y1 * sc + bi);
            }
        }
    }
}

// ---------------------------------------------------------------------------
extern "C" void kernel_launch(void* const* d_in, const int* in_sizes, int n_in,
                              void* d_out, int out_size) {
    const float* x     = (const float*)d_in[0];
    // d_in[1]=Wk, d_in[2]=Wq unused (softmax row-sums == 1 -> agg == V)
    const float* Wv    = (const float*)d_in[3];
    const float* Wout  = (const float*)d_in[4];
    const float* bout  = (const float*)d_in[5];
    const float* gamma = (const float*)d_in[6];
    const float* beta  = (const float*)d_in[7];
    float* out = (float*)d_out;

    cudaFuncSetAttribute(mega_kernel,
                         cudaFuncAttributeMaxDynamicSharedMemorySize, SMEM_BYTES);

    mega_kernel<<<NCTAS, NTHREADS, SMEM_BYTES>>>(x, Wv, Wout, bout, gamma, beta, out);
}

// round 10
// speedup vs baseline: 1.5645x; 1.1654x over previous
#include <cuda_runtime.h>
#include <cstdint>

#define CH    256
#define FF    512
#define NB    2048
#define BATCH 8
#define BN_COUNT 16384.0f
#define NCTAS 128u
#define NTHREADS 512

#define MT 128
#define NT 256
#define KC 32
#define A_STRIDE 264        // floats per A row; f2 stride 132 (LDS.64: conflict-free)
#define B_STRIDE 264        // floats per B row (bank 8t+r: bijective)

#define A_FL       (128 * A_STRIDE)         // 33792 floats
#define B_BUF_FL   (KC * B_STRIDE)          // 8448 floats
#define OFF_A      0
#define OFF_B      A_FL
#define OFF_RED    (A_FL + 2 * B_BUF_FL)    // 50688
#define SMEM_FL    (OFF_RED + 256)          // 50944
#define SMEM_BYTES (SMEM_FL * 4)            // 203776 B

// phase-0 scratch inside the (not yet used) A region
#define P0_WOUT   0                 // [16][516]  = 8256 floats
#define P0_WV     8256              // [512][36]  = 18432 floats -> ends 26688
#define P0_PART   27008             // [8][512]   = 4096 floats  -> ends 31104 (< 33792)

// Scratch globals (module-load zeroed; never re-zeroed)
__device__ float    g_Weff[CH * CH];        // column-PERMUTED layout (paired K)
__device__ float    g_part [128 * 128];
__device__ float    g_partq[128 * 128];
__device__ unsigned g_bar;                  // monotonic ticket counter

__device__ __forceinline__ uint32_t smem_u32(const void* p) {
    uint32_t a;
    asm("{ .reg .u64 t; cvta.to.shared.u64 t, %1; cvt.u32.u64 %0, t; }" : "=r"(a) : "l"(p));
    return a;
}
__device__ __forceinline__ void cp_async16(uint32_t dst, const void* src) {
    asm volatile("cp.async.cg.shared.global [%0], [%1], 16;" :: "r"(dst), "l"(src));
}
__device__ __forceinline__ void cp_commit() {
    asm volatile("cp.async.commit_group;");
}
__device__ __forceinline__ void mma_tf32(float* d, const uint32_t* a, const uint32_t* b) {
    asm volatile(
        "mma.sync.aligned.m16n8k8.row.col.f32.tf32.tf32.f32 "
        "{%0,%1,%2,%3}, {%4,%5,%6,%7}, {%8,%9}, {%0,%1,%2,%3};"
        : "+f"(d[0]), "+f"(d[1]), "+f"(d[2]), "+f"(d[3])
        : "r"(a[0]), "r"(a[1]), "r"(a[2]), "r"(a[3]), "r"(b[0]), "r"(b[1]));
}

// Monotonic grid barrier: no reset, generation from ticket value.
__device__ __forceinline__ void grid_barrier(int tid) {
    __syncthreads();
    if (tid == 0) {
        __threadfence();
        unsigned tck = atomicAdd(&g_bar, 1u);
        unsigned target = (tck & ~(NCTAS - 1u)) + NCTAS;
        unsigned v;
        do {
            asm volatile("ld.acquire.gpu.u32 %0, [%1];" : "=r"(v) : "l"(&g_bar));
        } while ((int)(v - target) < 0);
    }
    __syncthreads();
}

// Paired-K column permutation: within each 8-block, k -> (k%4)*2 + k/4
__device__ __forceinline__ int permc(int c) {
    return (c & ~7) | ((c & 3) << 1) | ((c >> 2) & 1);
}

// ---------------------------------------------------------------------------
// THE kernel. grid 128 (1/SM), 512 threads (16 warps).
// Phase 0: smem-tiled W_eff mini-GEMM (split-K x8, 2o x 4c register blocks).
// Barrier. tf32 mma mainloop (A resident, paired-K). Epi 1: y -> acc + BN
// partials. Barrier. Reduce. Epi 2: normalize register-resident y, store.
// ---------------------------------------------------------------------------
__global__ void __launch_bounds__(NTHREADS, 1)
mega_kernel(const float* __restrict__ x,
            const float* __restrict__ Wv,
            const float* __restrict__ Wout,
            const float* __restrict__ bout,
            const float* __restrict__ gamma,
            const float* __restrict__ beta,
            float* __restrict__ out) {
    extern __shared__ float smf[];
    uint32_t smb = smem_u32(smf);

    int tid  = threadIdx.x;
    int bid  = blockIdx.x;
    int wid  = tid >> 5;           // 0..15
    int lane = tid & 31;
    int r    = lane >> 2;          // 0..7
    int t    = lane & 3;           // 0..3
    int wRow = wid & 3;            // m * 32
    int wCol = wid >> 2;           // n * 64 (0..3)

    int xt    = bid & 7;
    int yt    = (bid >> 3) & 1;
    int zt    = bid >> 4;
    int n0    = xt * NT;
    int mBase = yt * MT;
    const float* xb = x   + (size_t)zt * CH * NB;
    float*       ob = out + (size_t)zt * CH * NB;

    // ---- prefetch first B chunk (independent of W_eff) ----
    #define LOAD_B(buf, k0)                                                    \
    {                                                                          \
        uint32_t bdst = smb + (OFF_B + (buf) * B_BUF_FL) * 4;                  \
        _Pragma("unroll")                                                      \
        for (int it = 0; it < 4; it++) {                                       \
            int e = tid + it * NTHREADS;  /* 0..2047 float4 slots */           \
            int k = e >> 6, n4 = e & 63;                                       \
            cp_async16(bdst + (k * B_STRIDE + n4 * 4) * 4,                     \
                       &xb[(size_t)((k0) + k) * NB + n0 + n4 * 4]);            \
        }                                                                      \
    }
    LOAD_B(0, 0);
    cp_commit();

    // ---- Phase 0: W_eff slice (16 o x 32 c per CTA), smem-tiled GEMM ----
    {
        int o0 = ((bid >> 3) & 15) * 16;
        int c0 = (bid & 7) * 32;
        float* wout_s = smf + P0_WOUT;     // [16][516]
        float* wv_s   = smf + P0_WV;       // [512][36]
        float* part_s = smf + P0_PART;     // [8][512]

        // stage Wout tile: 16 rows x 512 k (2048 float4, 4/thread, coalesced)
        #pragma unroll
        for (int it = 0; it < 4; it++) {
            int e = tid + it * NTHREADS;
            int o = e >> 7, k4 = e & 127;
            *(float4*)&wout_s[o * 516 + k4 * 4] =
                *(const float4*)&Wout[(size_t)(o0 + o) * FF + k4 * 4];
        }
        // stage Wv tile: 512 rows x 32 c (4096 float4, 8/thread)
        #pragma unroll
        for (int it = 0; it < 8; it++) {
            int e = tid + it * NTHREADS;
            int k = e >> 3, c4 = e & 7;
            *(float4*)&wv_s[k * 36 + c4 * 4] =
                *(const float4*)&Wv[(size_t)k * CH + c0 + c4 * 4];
        }
        __syncthreads();

        int ks = tid >> 6;             // 0..7 K-slice
        int oc = (tid >> 3) & 7;       // 0..7 -> o pair
        int cc = tid & 7;              // 0..7 -> c quad
        float a0[4] = {0.f, 0.f, 0.f, 0.f};
        float a1[4] = {0.f, 0.f, 0.f, 0.f};
        const float* w0p = &wout_s[(oc * 2 + 0) * 516];
        const float* w1p = &wout_s[(oc * 2 + 1) * 516];
        #pragma unroll 8
        for (int k = ks * 64; k < ks * 64 + 64; k++) {
            float4 v = *(const float4*)&wv_s[k * 36 + cc * 4];
            float w0 = w0p[k], w1 = w1p[k];
            a0[0] = fmaf(w0, v.x, a0[0]);
            a0[1] = fmaf(w0, v.y, a0[1]);
            a0[2] = fmaf(w0, v.z, a0[2]);
            a0[3] = fmaf(w0, v.w, a0[3]);
            a1[0] = fmaf(w1, v.x, a1[0]);
            a1[1] = fmaf(w1, v.y, a1[1]);
            a1[2] = fmaf(w1, v.z, a1[2]);
            a1[3] = fmaf(w1, v.w, a1[3]);
        }
        *(float4*)&part_s[ks * 512 + (oc * 2 + 0) * 32 + cc * 4] =
            make_float4(a0[0], a0[1], a0[2], a0[3]);
        *(float4*)&part_s[ks * 512 + (oc * 2 + 1) * 32 + cc * 4] =
            make_float4(a1[0], a1[1], a1[2], a1[3]);
        __syncthreads();

        // combine 8 K-slices; store with paired-K column permutation
        {
            int o = tid >> 5, c = tid & 31;
            float s = 0.f;
            #pragma unroll
            for (int j = 0; j < 8; j++) s += part_s[j * 512 + tid];
            g_Weff[(o0 + o) * CH + permc(c0 + c)] = s;
        }
    }
    grid_barrier(tid);              // W_eff globally visible

    // ---- A resident load: W_eff[mBase:+128, 0:256] -> smem (permuted cols) ----
    #pragma unroll
    for (int it = 0; it < 16; it++) {
        int e = tid + it * NTHREADS;     // 0..8191 float4 slots
        int m = e >> 6, c4 = e & 63;
        cp_async16(smb + (OFF_A + m * A_STRIDE + c4 * 4) * 4,
                   &g_Weff[(mBase + m) * CH + c4 * 4]);
    }
    cp_commit();

    if (tid < 256) smf[OFF_RED + tid] = 0.f;

    float acc[2][8][4];
    #pragma unroll
    for (int mt = 0; mt < 2; mt++)
        #pragma unroll
        for (int nt = 0; nt < 8; nt++)
            #pragma unroll
            for (int q = 0; q < 4; q++) acc[mt][nt][q] = 0.f;

    const uint2* Au2 = (const uint2*)(smf + OFF_A);

    // ---- mainloop: 8 K-chunks, double-buffered B ----
    for (int i = 0; i < 8; i++) {
        int buf = i & 1;
        if (i < 7) {
            LOAD_B((i + 1) & 1, (i + 1) * KC);
            cp_commit();
            asm volatile("cp.async.wait_group 1;");
        } else {
            asm volatile("cp.async.wait_group 0;");
        }
        __syncthreads();

        const uint32_t* Bu = (const uint32_t*)(smf + OFF_B + buf * B_BUF_FL);

        #pragma unroll
        for (int kc = 0; kc < 4; kc++) {
            int kk2 = i * 16 + kc * 4;   // paired-K f2 offset
            int bk8 = kc * 8;
            uint32_t afr[2][4];
            #pragma unroll
            for (int mt = 0; mt < 2; mt++) {
                int m = wRow * 32 + mt * 16 + r;
                uint2 p0 = Au2[m * 132 + kk2 + t];
                uint2 p1 = Au2[(m + 8) * 132 + kk2 + t];
                afr[mt][0] = p0.x;
                afr[mt][1] = p1.x;
                afr[mt][2] = p0.y;
                afr[mt][3] = p1.y;
            }
            #pragma unroll
            for (int nt = 0; nt < 8; nt++) {
                int n = wCol * 64 + nt * 8 + r;
                uint32_t bfr[2];
                bfr[0] = Bu[(bk8 + t) * B_STRIDE + n];
                bfr[1] = Bu[(bk8 + t + 4) * B_STRIDE + n];
                mma_tf32(acc[0][nt], afr[0], bfr);
                mma_tf32(acc[1][nt], afr[1], bfr);
            }
        }
        __syncthreads();
    }

    // ---- epilogue 1: fold y into acc, accumulate per-CTA BN partials ----
    float* s_red = smf + OFF_RED;
    #pragma unroll
    for (int mt = 0; mt < 2; mt++) {
        #pragma unroll
        for (int rv = 0; rv < 2; rv++) {
            int rl = wRow * 32 + mt * 16 + rv * 8 + r;
            int rg = mBase + rl;
            float bo = bout[rg];
            float ps = 0.f, pq = 0.f;
            #pragma unroll
            for (int nt = 0; nt < 8; nt++) {
                int col = n0 + wCol * 64 + nt * 8 + t * 2;
                size_t gi = (size_t)rg * NB + col;
                float2 xv = *(const float2*)&xb[gi];
                float y0 = xv.x + fmaxf(acc[mt][nt][rv * 2 + 0] + bo, 0.f);
                float y1 = xv.y + fmaxf(acc[mt][nt][rv * 2 + 1] + bo, 0.f);
                acc[mt][nt][rv * 2 + 0] = y0;   // acc now holds y
                acc[mt][nt][rv * 2 + 1] = y1;
                ps += y0 + y1;
                pq += y0 * y0 + y1 * y1;
            }
            atomicAdd(&s_red[rl], ps);
            atomicAdd(&s_red[128 + rl], pq);
        }
    }
    __syncthreads();
    if (tid < 128)
        g_part [bid * 128 + tid] = s_red[tid];
    else if (tid < 256)
        g_partq[bid * 128 + (tid - 128)] = s_red[tid];

    grid_barrier(tid);              // all partials visible

    // ---- reduce 64 partials (same m-tile: y==yt) ----
    if (tid < 128) {
        float s = 0.f;
        #pragma unroll 8
        for (int j = 0; j < 64; j++) {
            int pid = (j & 7) + 8 * yt + 16 * (j >> 3);
            s += g_part[pid * 128 + tid];
        }
        s_red[tid] = s;
    } else if (tid < 256) {
        int ch = tid - 128;
        float s = 0.f;
        #pragma unroll 8
        for (int j = 0; j < 64; j++) {
            int pid = (j & 7) + 8 * yt + 16 * (j >> 3);
            s += g_partq[pid * 128 + ch];
        }
        s_red[tid] = s;
    }
    __syncthreads();

    // ---- epilogue 2: normalize register-resident y, single store ----
    #pragma unroll
    for (int mt = 0; mt < 2; mt++) {
        #pragma unroll
        for (int rv = 0; rv < 2; rv++) {
            int rl = wRow * 32 + mt * 16 + rv * 8 + r;
            int rg = mBase + rl;
            float m  = s_red[rl]       * (1.0f / BN_COUNT);
            float vv = s_red[128 + rl] * (1.0f / BN_COUNT) - m * m;
            float sc = gamma[rg] * rsqrtf(vv + 1e-5f);
            float bi = beta[rg] - m * sc;
            #pragma unroll
            for (int nt = 0; nt < 8; nt++) {
                int col = n0 + wCol * 64 + nt * 8 + t * 2;
                size_t gi = (size_t)rg * NB + col;
                float y0 = acc[mt][nt][rv * 2 + 0];
                float y1 = acc[mt][nt][rv * 2 + 1];
                *(float2*)&ob[gi] = make_float2(y0 * sc + bi, y1 * sc + bi);
            }
        }
    }
}

// ---------------------------------------------------------------------------
extern "C" void kernel_launch(void* const* d_in, const int* in_sizes, int n_in,
                              void* d_out, int out_size) {
    const float* x     = (const float*)d_in[0];
    // d_in[1]=Wk, d_in[2]=Wq unused (softmax row-sums == 1 -> agg == V)
    const float* Wv    = (const float*)d_in[3];
    const float* Wout  = (const float*)d_in[4];
    const float* bout  = (const float*)d_in[5];
    const float* gamma = (const float*)d_in[6];
    const float* beta  = (const float*)d_in[7];
    float* out = (float*)d_out;

    cudaFuncSetAttribute(mega_kernel,
                         cudaFuncAttributeMaxDynamicSharedMemorySize, SMEM_BYTES);

    mega_kernel<<<NCTAS, NTHREADS, SMEM_BYTES>>>(x, Wv, Wout, bout, gamma, beta, out);
}

// round 12
// speedup vs baseline: 1.7210x; 1.1000x over previous
#include <cuda_runtime.h>
#include <cstdint>

#define CH    256
#define FF    512
#define NB    2048
#define BATCH 8
#define BN_COUNT 16384.0f
#define NCTAS 128u
#define NTHREADS 512

#define MT 128
#define NT 256
#define KC 32
#define A_STRIDE 264        // floats per A row; f2 stride 132 (LDS.64: conflict-free)
#define B_STRIDE 264        // floats per B row (bank 8t+r: bijective)

#define A_FL       (128 * A_STRIDE)         // 33792 floats
#define B_BUF_FL   (KC * B_STRIDE)          // 8448 floats
#define OFF_A      0
#define OFF_B      A_FL
#define OFF_RED    (A_FL + 2 * B_BUF_FL)    // 50688
#define SMEM_FL    (OFF_RED + 1280)         // 51968: s_red[256] + comb[1024]
#define SMEM_BYTES (SMEM_FL * 4)            // 207872 B (fits 227KB carveout)

// phase-0 scratch inside the (not yet used) A region
#define P0_WOUT   0                 // [16][516]  = 8256 floats
#define P0_WV     8256              // [512][36]  = 18432 floats -> ends 26688
#define P0_PART   27008             // [8][512]   = 4096 floats  -> ends 31104 (< 33792)

// Scratch globals (module-load zeroed; never re-zeroed)
__device__ float    g_Weff[CH * CH];        // column-PERMUTED layout (paired K)
__device__ float    g_part [128 * 128];
__device__ float    g_partq[128 * 128];
__device__ unsigned g_bar;                  // monotonic ticket counter

__device__ __forceinline__ uint32_t smem_u32(const void* p) {
    uint32_t a;
    asm("{ .reg .u64 t; cvta.to.shared.u64 t, %1; cvt.u32.u64 %0, t; }" : "=r"(a) : "l"(p));
    return a;
}
__device__ __forceinline__ void cp_async16(uint32_t dst, const void* src) {
    asm volatile("cp.async.cg.shared.global [%0], [%1], 16;" :: "r"(dst), "l"(src));
}
__device__ __forceinline__ void cp_commit() {
    asm volatile("cp.async.commit_group;");
}
__device__ __forceinline__ void mma_tf32(float* d, const uint32_t* a, const uint32_t* b) {
    asm volatile(
        "mma.sync.aligned.m16n8k8.row.col.f32.tf32.tf32.f32 "
        "{%0,%1,%2,%3}, {%4,%5,%6,%7}, {%8,%9}, {%0,%1,%2,%3};"
        : "+f"(d[0]), "+f"(d[1]), "+f"(d[2]), "+f"(d[3])
        : "r"(a[0]), "r"(a[1]), "r"(a[2]), "r"(a[3]), "r"(b[0]), "r"(b[1]));
}

// Monotonic grid barrier: no reset, generation from ticket value.
__device__ __forceinline__ void grid_barrier(int tid) {
    __syncthreads();
    if (tid == 0) {
        __threadfence();
        unsigned tck = atomicAdd(&g_bar, 1u);
        unsigned target = (tck & ~(NCTAS - 1u)) + NCTAS;
        unsigned v;
        do {
            asm volatile("ld.acquire.gpu.u32 %0, [%1];" : "=r"(v) : "l"(&g_bar));
        } while ((int)(v - target) < 0);
    }
    __syncthreads();
}

// Paired-K column permutation: within each 8-block, k -> (k%4)*2 + k/4
__device__ __forceinline__ int permc(int c) {
    return (c & ~7) | ((c & 3) << 1) | ((c >> 2) & 1);
}

// ---------------------------------------------------------------------------
// THE kernel. grid 128 (1/SM), 512 threads (16 warps).
// Phase 0: smem-tiled W_eff mini-GEMM. Barrier. Fully-unrolled tf32 mma
// mainloop (A resident, paired-K, hoisted pointers). Epi 1: y -> acc + BN
// partials (quad-reduced atomics). Barrier. Balanced reduce. Epi 2: store.
// ---------------------------------------------------------------------------
__global__ void __launch_bounds__(NTHREADS, 1)
mega_kernel(const float* __restrict__ x,
            const float* __restrict__ Wv,
            const float* __restrict__ Wout,
            const float* __restrict__ bout,
            const float* __restrict__ gamma,
            const float* __restrict__ beta,
            float* __restrict__ out) {
    extern __shared__ float smf[];
    uint32_t smb = smem_u32(smf);

    int tid  = threadIdx.x;
    int bid  = blockIdx.x;
    int wid  = tid >> 5;           // 0..15
    int lane = tid & 31;
    int r    = lane >> 2;          // 0..7
    int t    = lane & 3;           // 0..3
    int wRow = wid & 3;            // m * 32
    int wCol = wid >> 2;           // n * 64 (0..3)

    int xt    = bid & 7;
    int yt    = (bid >> 3) & 1;
    int zt    = bid >> 4;
    int n0    = xt * NT;
    int mBase = yt * MT;
    const float* xb = x   + (size_t)zt * CH * NB;
    float*       ob = out + (size_t)zt * CH * NB;

    // ---- hoisted B-load bases (thread-invariant across chunks) ----
    const float* bsrc0 = &xb[(size_t)(tid >> 6) * NB + n0 + (tid & 63) * 4];
    uint32_t     bdst0 = smb + (OFF_B + (tid >> 6) * B_STRIDE + (tid & 63) * 4) * 4;

    #define LOAD_B(buf, k0)                                                    \
    {                                                                          \
        _Pragma("unroll")                                                      \
        for (int it = 0; it < 4; it++)                                         \
            cp_async16(bdst0 + (buf) * (B_BUF_FL * 4) + it * (8 * B_STRIDE * 4),\
                       bsrc0 + (size_t)(k0 + it * 8) * NB);                    \
    }
    LOAD_B(0, 0);
    cp_commit();

    // ---- Phase 0: W_eff slice (16 o x 32 c per CTA), smem-tiled GEMM ----
    {
        int o0 = ((bid >> 3) & 15) * 16;
        int c0 = (bid & 7) * 32;
        float* wout_s = smf + P0_WOUT;     // [16][516]
        float* wv_s   = smf + P0_WV;       // [512][36]
        float* part_s = smf + P0_PART;     // [8][512]

        #pragma unroll
        for (int it = 0; it < 4; it++) {
            int e = tid + it * NTHREADS;
            int o = e >> 7, k4 = e & 127;
            *(float4*)&wout_s[o * 516 + k4 * 4] =
                *(const float4*)&Wout[(size_t)(o0 + o) * FF + k4 * 4];
        }
        #pragma unroll
        for (int it = 0; it < 8; it++) {
            int e = tid + it * NTHREADS;
            int k = e >> 3, c4 = e & 7;
            *(float4*)&wv_s[k * 36 + c4 * 4] =
                *(const float4*)&Wv[(size_t)k * CH + c0 + c4 * 4];
        }
        __syncthreads();

        int ks = tid >> 6;             // 0..7 K-slice
        int oc = (tid >> 3) & 7;       // 0..7 -> o pair
        int cc = tid & 7;              // 0..7 -> c quad
        float a0[4] = {0.f, 0.f, 0.f, 0.f};
        float a1[4] = {0.f, 0.f, 0.f, 0.f};
        const float* w0p = &wout_s[(oc * 2 + 0) * 516];
        const float* w1p = &wout_s[(oc * 2 + 1) * 516];
        #pragma unroll 8
        for (int k = ks * 64; k < ks * 64 + 64; k++) {
            float4 v = *(const float4*)&wv_s[k * 36 + cc * 4];
            float w0 = w0p[k], w1 = w1p[k];
            a0[0] = fmaf(w0, v.x, a0[0]);
            a0[1] = fmaf(w0, v.y, a0[1]);
            a0[2] = fmaf(w0, v.z, a0[2]);
            a0[3] = fmaf(w0, v.w, a0[3]);
            a1[0] = fmaf(w1, v.x, a1[0]);
            a1[1] = fmaf(w1, v.y, a1[1]);
            a1[2] = fmaf(w1, v.z, a1[2]);
            a1[3] = fmaf(w1, v.w, a1[3]);
        }
        *(float4*)&part_s[ks * 512 + (oc * 2 + 0) * 32 + cc * 4] =
            make_float4(a0[0], a0[1], a0[2], a0[3]);
        *(float4*)&part_s[ks * 512 + (oc * 2 + 1) * 32 + cc * 4] =
            make_float4(a1[0], a1[1], a1[2], a1[3]);
        __syncthreads();

        {
            int o = tid >> 5, c = tid & 31;
            float s = 0.f;
            #pragma unroll
            for (int j = 0; j < 8; j++) s += part_s[j * 512 + tid];
            g_Weff[(o0 + o) * CH + permc(c0 + c)] = s;
        }
    }
    grid_barrier(tid);              // W_eff globally visible

    // ---- A resident load: W_eff[mBase:+128, 0:256] -> smem (permuted cols) ----
    {
        const float* asrc0 = &g_Weff[(mBase + (tid >> 6)) * CH + (tid & 63) * 4];
        uint32_t     adst0 = smb + (OFF_A + (tid >> 6) * A_STRIDE + (tid & 63) * 4) * 4;
        #pragma unroll
        for (int it = 0; it < 16; it++)
            cp_async16(adst0 + it * (8 * A_STRIDE * 4), asrc0 + it * 8 * CH);
    }
    cp_commit();

    if (tid < 256) smf[OFF_RED + tid] = 0.f;

    float acc[2][8][4];
    #pragma unroll
    for (int mt = 0; mt < 2; mt++)
        #pragma unroll
        for (int nt = 0; nt < 8; nt++)
            #pragma unroll
            for (int q = 0; q < 4; q++) acc[mt][nt][q] = 0.f;

    // hoisted fragment base pointers
    const uint2*    aP  = (const uint2*)(smf + OFF_A) + (wRow * 32 + r) * 132 + t;
    const uint32_t* bP0 = (const uint32_t*)(smf + OFF_B) + t * B_STRIDE + wCol * 64 + r;

    // ---- mainloop: 8 K-chunks, fully unrolled, double-buffered B ----
    #pragma unroll
    for (int i = 0; i < 8; i++) {
        int buf = i & 1;
        if (i < 7) {
            LOAD_B((i + 1) & 1, (i + 1) * KC);
            cp_commit();
            asm volatile("cp.async.wait_group 1;");
        } else {
            asm volatile("cp.async.wait_group 0;");
        }
        __syncthreads();

        const uint32_t* bP = bP0 + buf * B_BUF_FL;

        #pragma unroll
        for (int kc = 0; kc < 4; kc++) {
            int kk2 = i * 16 + kc * 4;
            uint32_t afr[2][4];
            #pragma unroll
            for (int mt = 0; mt < 2; mt++) {
                uint2 p0 = aP[mt * (16 * 132) + kk2];
                uint2 p1 = aP[mt * (16 * 132) + 8 * 132 + kk2];
                afr[mt][0] = p0.x;
                afr[mt][1] = p1.x;
                afr[mt][2] = p0.y;
                afr[mt][3] = p1.y;
            }
            #pragma unroll
            for (int nt = 0; nt < 8; nt++) {
                uint32_t bfr[2];
                bfr[0] = bP[kc * (8 * B_STRIDE) + nt * 8];
                bfr[1] = bP[kc * (8 * B_STRIDE) + 4 * B_STRIDE + nt * 8];
                mma_tf32(acc[0][nt], afr[0], bfr);
                mma_tf32(acc[1][nt], afr[1], bfr);
            }
        }
        __syncthreads();
    }

    // ---- epilogue 1: fold y into acc, quad-reduced BN partials ----
    float* s_red = smf + OFF_RED;
    #pragma unroll
    for (int mt = 0; mt < 2; mt++) {
        #pragma unroll
        for (int rv = 0; rv < 2; rv++) {
            int rl = wRow * 32 + mt * 16 + rv * 8 + r;
            int rg = mBase + rl;
            float bo = bout[rg];
            float ps = 0.f, pq = 0.f;
            #pragma unroll
            for (int nt = 0; nt < 8; nt++) {
                int col = n0 + wCol * 64 + nt * 8 + t * 2;
                size_t gi = (size_t)rg * NB + col;
                float2 xv = *(const float2*)&xb[gi];
                float y0 = xv.x + fmaxf(acc[mt][nt][rv * 2 + 0] + bo, 0.f);
                float y1 = xv.y + fmaxf(acc[mt][nt][rv * 2 + 1] + bo, 0.f);
                acc[mt][nt][rv * 2 + 0] = y0;   // acc now holds y
                acc[mt][nt][rv * 2 + 1] = y1;
                ps += y0 + y1;
                pq += y0 * y0 + y1 * y1;
            }
            // reduce across the t-quad (lanes r*4 .. r*4+3), then 1 atomic
            ps += __shfl_xor_sync(0xFFFFFFFFu, ps, 1);
            ps += __shfl_xor_sync(0xFFFFFFFFu, ps, 2);
            pq += __shfl_xor_sync(0xFFFFFFFFu, pq, 1);
            pq += __shfl_xor_sync(0xFFFFFFFFu, pq, 2);
            if (t == 0) {
                atomicAdd(&s_red[rl], ps);
                atomicAdd(&s_red[128 + rl], pq);
            }
        }
    }
    __syncthreads();
    if (tid < 128)
        g_part [bid * 128 + tid] = s_red[tid];
    else if (tid < 256)
        g_partq[bid * 128 + (tid - 128)] = s_red[tid];

    grid_barrier(tid);              // all partials visible

    // ---- balanced reduce: 512 threads x (16+16) loads -> combine 4 ----
    {
        float* comb = smf + OFF_RED + 256;      // [4 groups][128 ch] sum + sumsq
        int ch  = tid & 127;
        int grp = tid >> 7;                     // 0..3, 16 pids each
        float s = 0.f, q = 0.f;
        #pragma unroll
        for (int jj = 0; jj < 16; jj++) {
            int j = grp * 16 + jj;
            int pid = (j & 7) + 8 * yt + 16 * (j >> 3);
            s += g_part [pid * 128 + ch];
            q += g_partq[pid * 128 + ch];
        }
        comb[grp * 128 + ch] = s;
        comb[512 + grp * 128 + ch] = q;
        __syncthreads();
        if (tid < 128) {
            s_red[tid] = comb[tid] + comb[128 + tid] + comb[256 + tid] + comb[384 + tid];
        } else if (tid < 256) {
            int c2 = tid - 128;
            s_red[tid] = comb[512 + c2] + comb[640 + c2] + comb[768 + c2] + comb[896 + c2];
        }
        __syncthreads();
    }

    // ---- epilogue 2: normalize register-resident y, single store ----
    #pragma unroll
    for (int mt = 0; mt < 2; mt++) {
        #pragma unroll
        for (int rv = 0; rv < 2; rv++) {
            int rl = wRow * 32 + mt * 16 + rv * 8 + r;
            int rg = mBase + rl;
            float m  = s_red[rl]       * (1.0f / BN_COUNT);
            float vv = s_red[128 + rl] * (1.0f / BN_COUNT) - m * m;
            float sc = gamma[rg] * rsqrtf(vv + 1e-5f);
            float bi = beta[rg] - m * sc;
            #pragma unroll
            for (int nt = 0; nt < 8; nt++) {
                int col = n0 + wCol * 64 + nt * 8 + t * 2;
                size_t gi = (size_t)rg * NB + col;
                float y0 = acc[mt][nt][rv * 2 + 0];
                float y1 = acc[mt][nt][rv * 2 + 1];
                *(float2*)&ob[gi] = make_float2(y0 * sc + bi, y1 * sc + bi);
            }
        }
    }
}

// ---------------------------------------------------------------------------
extern "C" void kernel_launch(void* const* d_in, const int* in_sizes, int n_in,
                              void* d_out, int out_size) {
    const float* x     = (const float*)d_in[0];
    // d_in[1]=Wk, d_in[2]=Wq unused (softmax row-sums == 1 -> agg == V)
    const float* Wv    = (const float*)d_in[3];
    const float* Wout  = (const float*)d_in[4];
    const float* bout  = (const float*)d_in[5];
    const float* gamma = (const float*)d_in[6];
    const float* beta  = (const float*)d_in[7];
    float* out = (float*)d_out;

    cudaFuncSetAttribute(mega_kernel,
                         cudaFuncAttributeMaxDynamicSharedMemorySize, SMEM_BYTES);

    mega_kernel<<<NCTAS, NTHREADS, SMEM_BYTES>>>(x, Wv, Wout, bout, gamma, beta, out);
}

// round 13
// speedup vs baseline: 1.7408x; 1.0116x over previous
#include <cuda_runtime.h>
#include <cstdint>

#define CH    256
#define FF    512
#define NB    2048
#define BATCH 8
#define BN_COUNT 16384.0f
#define NCTAS 128u
#define NTHREADS 512

#define MT 128
#define NT 256
#define KC 32
#define A_STRIDE 264        // floats per A row; f2 stride 132 (LDS.64: conflict-free)
#define B_STRIDE 264        // floats per B row (bank 8t+r: bijective)

#define A_FL       (128 * A_STRIDE)         // 33792 floats
#define B_BUF_FL   (KC * B_STRIDE)          // 8448 floats
#define OFF_A      0
#define OFF_B      A_FL
#define OFF_RED    (A_FL + 2 * B_BUF_FL)    // 50688
#define SMEM_FL    (OFF_RED + 256)          // 50944
#define SMEM_BYTES (SMEM_FL * 4)            // 203776 B

// phase-0 scratch inside the (not yet used) A region
#define P0_WOUT   0                 // [16][516]  = 8256 floats
#define P0_WV     8256              // [512][36]  = 18432 floats -> ends 26688
#define P0_PART   27008             // [8][512]   = 4096 floats  -> ends 31104 (< 33792)

// Scratch globals (module-load zeroed; g_sum/g_sumsq re-zeroed per launch
// by bid 0 in phase 0, sequenced by grid barrier 1 before any atomics)
__device__ float    g_Weff[CH * CH];        // column-PERMUTED layout (paired K)
__device__ float    g_sum  [CH];
__device__ float    g_sumsq[CH];
__device__ unsigned g_bar;                  // monotonic ticket counter

__device__ __forceinline__ uint32_t smem_u32(const void* p) {
    uint32_t a;
    asm("{ .reg .u64 t; cvta.to.shared.u64 t, %1; cvt.u32.u64 %0, t; }" : "=r"(a) : "l"(p));
    return a;
}
__device__ __forceinline__ void cp_async16(uint32_t dst, const void* src) {
    asm volatile("cp.async.cg.shared.global [%0], [%1], 16;" :: "r"(dst), "l"(src));
}
__device__ __forceinline__ void cp_commit() {
    asm volatile("cp.async.commit_group;");
}
__device__ __forceinline__ void mma_tf32(float* d, const uint32_t* a, const uint32_t* b) {
    asm volatile(
        "mma.sync.aligned.m16n8k8.row.col.f32.tf32.tf32.f32 "
        "{%0,%1,%2,%3}, {%4,%5,%6,%7}, {%8,%9}, {%0,%1,%2,%3};"
        : "+f"(d[0]), "+f"(d[1]), "+f"(d[2]), "+f"(d[3])
        : "r"(a[0]), "r"(a[1]), "r"(a[2]), "r"(a[3]), "r"(b[0]), "r"(b[1]));
}

// Monotonic grid barrier: no reset, generation from ticket value.
__device__ __forceinline__ void grid_barrier(int tid) {
    __syncthreads();
    if (tid == 0) {
        __threadfence();
        unsigned tck = atomicAdd(&g_bar, 1u);
        unsigned target = (tck & ~(NCTAS - 1u)) + NCTAS;
        unsigned v;
        do {
            asm volatile("ld.acquire.gpu.u32 %0, [%1];" : "=r"(v) : "l"(&g_bar));
        } while ((int)(v - target) < 0);
    }
    __syncthreads();
}

// Paired-K column permutation: within each 8-block, k -> (k%4)*2 + k/4
__device__ __forceinline__ int permc(int c) {
    return (c & ~7) | ((c & 3) << 1) | ((c >> 2) & 1);
}

// ---------------------------------------------------------------------------
// THE kernel. grid 128 (1/SM), 512 threads (16 warps).
// Phase 0: smem-tiled W_eff mini-GEMM (+ bid0 zeroes BN sums). Barrier.
// Fully-unrolled tf32 mma mainloop (A resident, paired-K). Epi 1: y -> acc,
// quad-reduced smem partials, ONE global atomic per channel slot. Barrier.
// Epi 2: read stats via L2, normalize register-resident y, store.
// ---------------------------------------------------------------------------
__global__ void __launch_bounds__(NTHREADS, 1)
mega_kernel(const float* __restrict__ x,
            const float* __restrict__ Wv,
            const float* __restrict__ Wout,
            const float* __restrict__ bout,
            const float* __restrict__ gamma,
            const float* __restrict__ beta,
            float* __restrict__ out) {
    extern __shared__ float smf[];
    uint32_t smb = smem_u32(smf);

    int tid  = threadIdx.x;
    int bid  = blockIdx.x;
    int wid  = tid >> 5;           // 0..15
    int lane = tid & 31;
    int r    = lane >> 2;          // 0..7
    int t    = lane & 3;           // 0..3
    int wRow = wid & 3;            // m * 32
    int wCol = wid >> 2;           // n * 64 (0..3)

    int xt    = bid & 7;
    int yt    = (bid >> 3) & 1;
    int zt    = bid >> 4;
    int n0    = xt * NT;
    int mBase = yt * MT;
    const float* xb = x   + zt * (CH * NB);      // 32-bit offsets below
    float*       ob = out + zt * (CH * NB);

    // ---- hoisted B-load bases (thread-invariant across chunks) ----
    const float* bsrc0 = xb + (tid >> 6) * NB + n0 + (tid & 63) * 4;
    uint32_t     bdst0 = smb + (OFF_B + (tid >> 6) * B_STRIDE + (tid & 63) * 4) * 4;

    #define LOAD_B(buf, k0)                                                    \
    {                                                                          \
        _Pragma("unroll")                                                      \
        for (int it = 0; it < 4; it++)                                         \
            cp_async16(bdst0 + (buf) * (B_BUF_FL * 4) + it * (8 * B_STRIDE * 4),\
                       bsrc0 + (k0 + it * 8) * NB);                            \
    }
    LOAD_B(0, 0);
    cp_commit();

    // ---- Phase 0: W_eff slice (16 o x 32 c per CTA), smem-tiled GEMM ----
    {
        int o0 = ((bid >> 3) & 15) * 16;
        int c0 = (bid & 7) * 32;
        float* wout_s = smf + P0_WOUT;     // [16][516]
        float* wv_s   = smf + P0_WV;       // [512][36]
        float* part_s = smf + P0_PART;     // [8][512]

        // bid 0 re-zeroes BN accumulators (visible to all after barrier 1)
        if (bid == 0) {
            if (tid < 256)      g_sum  [tid]       = 0.f;
            else                g_sumsq[tid - 256] = 0.f;
        }

        #pragma unroll
        for (int it = 0; it < 4; it++) {
            int e = tid + it * NTHREADS;
            int o = e >> 7, k4 = e & 127;
            *(float4*)&wout_s[o * 516 + k4 * 4] =
                *(const float4*)&Wout[(o0 + o) * FF + k4 * 4];
        }
        #pragma unroll
        for (int it = 0; it < 8; it++) {
            int e = tid + it * NTHREADS;
            int k = e >> 3, c4 = e & 7;
            *(float4*)&wv_s[k * 36 + c4 * 4] =
                *(const float4*)&Wv[k * CH + c0 + c4 * 4];
        }
        __syncthreads();

        int ks = tid >> 6;             // 0..7 K-slice
        int oc = (tid >> 3) & 7;       // 0..7 -> o pair
        int cc = tid & 7;              // 0..7 -> c quad
        float a0[4] = {0.f, 0.f, 0.f, 0.f};
        float a1[4] = {0.f, 0.f, 0.f, 0.f};
        const float* w0p = &wout_s[(oc * 2 + 0) * 516];
        const float* w1p = &wout_s[(oc * 2 + 1) * 516];
        #pragma unroll 8
        for (int k = ks * 64; k < ks * 64 + 64; k++) {
            float4 v = *(const float4*)&wv_s[k * 36 + cc * 4];
            float w0 = w0p[k], w1 = w1p[k];
            a0[0] = fmaf(w0, v.x, a0[0]);
            a0[1] = fmaf(w0, v.y, a0[1]);
            a0[2] = fmaf(w0, v.z, a0[2]);
            a0[3] = fmaf(w0, v.w, a0[3]);
            a1[0] = fmaf(w1, v.x, a1[0]);
            a1[1] = fmaf(w1, v.y, a1[1]);
            a1[2] = fmaf(w1, v.z, a1[2]);
            a1[3] = fmaf(w1, v.w, a1[3]);
        }
        *(float4*)&part_s[ks * 512 + (oc * 2 + 0) * 32 + cc * 4] =
            make_float4(a0[0], a0[1], a0[2], a0[3]);
        *(float4*)&part_s[ks * 512 + (oc * 2 + 1) * 32 + cc * 4] =
            make_float4(a1[0], a1[1], a1[2], a1[3]);
        __syncthreads();

        {
            int o = tid >> 5, c = tid & 31;
            float s = 0.f;
            #pragma unroll
            for (int j = 0; j < 8; j++) s += part_s[j * 512 + tid];
            g_Weff[(o0 + o) * CH + permc(c0 + c)] = s;
        }
    }
    grid_barrier(tid);              // W_eff + zeroed sums globally visible

    // ---- A resident load: W_eff[mBase:+128, 0:256] -> smem (permuted cols) ----
    {
        const float* asrc0 = &g_Weff[(mBase + (tid >> 6)) * CH + (tid & 63) * 4];
        uint32_t     adst0 = smb + (OFF_A + (tid >> 6) * A_STRIDE + (tid & 63) * 4) * 4;
        #pragma unroll
        for (int it = 0; it < 16; it++)
            cp_async16(adst0 + it * (8 * A_STRIDE * 4), asrc0 + it * 8 * CH);
    }
    cp_commit();

    if (tid < 256) smf[OFF_RED + tid] = 0.f;

    float acc[2][8][4];
    #pragma unroll
    for (int mt = 0; mt < 2; mt++)
        #pragma unroll
        for (int nt = 0; nt < 8; nt++)
            #pragma unroll
            for (int q = 0; q < 4; q++) acc[mt][nt][q] = 0.f;

    // hoisted fragment base pointers
    const uint2*    aP  = (const uint2*)(smf + OFF_A) + (wRow * 32 + r) * 132 + t;
    const uint32_t* bP0 = (const uint32_t*)(smf + OFF_B) + t * B_STRIDE + wCol * 64 + r;

    // ---- mainloop: 8 K-chunks, fully unrolled, double-buffered B ----
    #pragma unroll
    for (int i = 0; i < 8; i++) {
        int buf = i & 1;
        if (i < 7) {
            LOAD_B((i + 1) & 1, (i + 1) * KC);
            cp_commit();
            asm volatile("cp.async.wait_group 1;");
        } else {
            asm volatile("cp.async.wait_group 0;");
        }
        __syncthreads();

        const uint32_t* bP = bP0 + buf * B_BUF_FL;

        #pragma unroll
        for (int kc = 0; kc < 4; kc++) {
            int kk2 = i * 16 + kc * 4;
            uint32_t afr[2][4];
            #pragma unroll
            for (int mt = 0; mt < 2; mt++) {
                uint2 p0 = aP[mt * (16 * 132) + kk2];
                uint2 p1 = aP[mt * (16 * 132) + 8 * 132 + kk2];
                afr[mt][0] = p0.x;
                afr[mt][1] = p1.x;
                afr[mt][2] = p0.y;
                afr[mt][3] = p1.y;
            }
            #pragma unroll
            for (int nt = 0; nt < 8; nt++) {
                uint32_t bfr[2];
                bfr[0] = bP[kc * (8 * B_STRIDE) + nt * 8];
                bfr[1] = bP[kc * (8 * B_STRIDE) + 4 * B_STRIDE + nt * 8];
                mma_tf32(acc[0][nt], afr[0], bfr);
                mma_tf32(acc[1][nt], afr[1], bfr);
            }
        }
        __syncthreads();
    }

    // ---- epilogue 1: fold y into acc, quad-reduced smem partials ----
    float* s_red = smf + OFF_RED;
    #pragma unroll
    for (int mt = 0; mt < 2; mt++) {
        #pragma unroll
        for (int rv = 0; rv < 2; rv++) {
            int rl = wRow * 32 + mt * 16 + rv * 8 + r;
            int rg = mBase + rl;
            float bo = bout[rg];
            int rowOff = rg * NB + n0 + wCol * 64 + t * 2;   // 32-bit
            float ps = 0.f, pq = 0.f;
            #pragma unroll
            for (int nt = 0; nt < 8; nt++) {
                float2 xv = *(const float2*)(xb + rowOff + nt * 8);
                float y0 = xv.x + fmaxf(acc[mt][nt][rv * 2 + 0] + bo, 0.f);
                float y1 = xv.y + fmaxf(acc[mt][nt][rv * 2 + 1] + bo, 0.f);
                acc[mt][nt][rv * 2 + 0] = y0;   // acc now holds y
                acc[mt][nt][rv * 2 + 1] = y1;
                ps += y0 + y1;
                pq += y0 * y0 + y1 * y1;
            }
            ps += __shfl_xor_sync(0xFFFFFFFFu, ps, 1);
            ps += __shfl_xor_sync(0xFFFFFFFFu, ps, 2);
            pq += __shfl_xor_sync(0xFFFFFFFFu, pq, 1);
            pq += __shfl_xor_sync(0xFFFFFFFFu, pq, 2);
            if (t == 0) {
                atomicAdd(&s_red[rl], ps);
                atomicAdd(&s_red[128 + rl], pq);
            }
        }
    }
    __syncthreads();
    // ONE global atomic per channel slot (256 per CTA)
    if (tid < 128)
        atomicAdd(&g_sum[mBase + tid], s_red[tid]);
    else if (tid < 256)
        atomicAdd(&g_sumsq[mBase + (tid - 128)], s_red[tid]);

    grid_barrier(tid);              // all channel sums final

    // ---- epilogue 2: read stats (L2), normalize register-resident y ----
    float scv[2][2], biv[2][2];
    #pragma unroll
    for (int mt = 0; mt < 2; mt++) {
        #pragma unroll
        for (int rv = 0; rv < 2; rv++) {
            int rg = mBase + wRow * 32 + mt * 16 + rv * 8 + r;
            float s = __ldcg(&g_sum[rg]);
            float q = __ldcg(&g_sumsq[rg]);
            float m  = s * (1.0f / BN_COUNT);
            float vv = q * (1.0f / BN_COUNT) - m * m;
            float sc = gamma[rg] * rsqrtf(vv + 1e-5f);
            scv[mt][rv] = sc;
            biv[mt][rv] = beta[rg] - m * sc;
        }
    }
    #pragma unroll
    for (int mt = 0; mt < 2; mt++) {
        #pragma unroll
        for (int rv = 0; rv < 2; rv++) {
            int rg = mBase + wRow * 32 + mt * 16 + rv * 8 + r;
            int rowOff = rg * NB + n0 + wCol * 64 + t * 2;   // 32-bit
            float sc = scv[mt][rv], bi = biv[mt][rv];
            #pragma unroll
            for (int nt = 0; nt < 8; nt++) {
                float y0 = acc[mt][nt][rv * 2 + 0];
                float y1 = acc[mt][nt][rv * 2 + 1];
                *(float2*)(ob + rowOff + nt * 8) =
                    make_float2(y0 * sc + bi, y1 * sc + bi);
            }
        }
    }
}

// ---------------------------------------------------------------------------
extern "C" void kernel_launch(void* const* d_in, const int* in_sizes, int n_in,
                              void* d_out, int out_size) {
    const float* x     = (const float*)d_in[0];
    // d_in[1]=Wk, d_in[2]=Wq unused (softmax row-sums == 1 -> agg == V)
    const float* Wv    = (const float*)d_in[3];
    const float* Wout  = (const float*)d_in[4];
    const float* bout  = (const float*)d_in[5];
    const float* gamma = (const float*)d_in[6];
    const float* beta  = (const float*)d_in[7];
    float* out = (float*)d_out;

    cudaFuncSetAttribute(mega_kernel,
                         cudaFuncAttributeMaxDynamicSharedMemorySize, SMEM_BYTES);

    mega_kernel<<<NCTAS, NTHREADS, SMEM_BYTES>>>(x, Wv, Wout, bout, gamma, beta, out);
}